// round 4
// baseline (speedup 1.0000x reference)
#include <cuda_runtime.h>
#include <cstdint>

#define S_LEN 2048
#define D_DIM 1024
#define NH    16
#define HDIM  64
#define NB    2
#define M_TOT 4096

// Scratch
__device__ float g_q[NB * NH * S_LEN * HDIM];   // [b,h,s,hd], pre-scaled 0.125, tf32
__device__ float g_k[NB * NH * S_LEN * HDIM];
__device__ float g_v[NB * NH * S_LEN * HDIM];
__device__ float g_ctx[NB * S_LEN * D_DIM];     // [b,s,d], tf32-rounded
__device__ float g_xc[M_TOT * D_DIM];           // tf32-rounded copies of inputs
__device__ float g_wqc[D_DIM * D_DIM];
__device__ float g_wkc[D_DIM * D_DIM];
__device__ float g_wvc[D_DIM * D_DIM];
__device__ float g_woc[D_DIM * D_DIM];

// ---------------------------------------------------------------------------
__device__ __forceinline__ uint32_t f2tf(float f) {
    uint32_t u;
    asm("cvt.rna.tf32.f32 %0, %1;" : "=r"(u) : "f"(f));
    return u;
}
__device__ __forceinline__ float u2f(uint32_t u) { return __uint_as_float(u); }
__device__ __forceinline__ uint32_t fbits(float f) { return __float_as_uint(f); }

__device__ __forceinline__ uint32_t smem_u32(const void* p) {
    uint32_t a;
    asm("{ .reg .u64 t; cvta.to.shared.u64 t, %1; cvt.u32.u64 %0, t; }" : "=r"(a) : "l"(p));
    return a;
}
__device__ __forceinline__ void mma_tf32(float d[4], const uint32_t a[4], const uint32_t b[2]) {
    asm("mma.sync.aligned.m16n8k8.row.col.f32.tf32.tf32.f32 "
        "{%0,%1,%2,%3}, {%4,%5,%6,%7}, {%8,%9}, {%0,%1,%2,%3};"
        : "+f"(d[0]), "+f"(d[1]), "+f"(d[2]), "+f"(d[3])
        : "r"(a[0]), "r"(a[1]), "r"(a[2]), "r"(a[3]), "r"(b[0]), "r"(b[1]));
}
__device__ __forceinline__ void cpa16(uint32_t dst, const void* src) {
    asm volatile("cp.async.ca.shared.global [%0], [%1], 16;" :: "r"(dst), "l"(src) : "memory");
}
__device__ __forceinline__ void cpa_commit() {
    asm volatile("cp.async.commit_group;" ::: "memory");
}
template <int N>
__device__ __forceinline__ void cpa_wait() {
    asm volatile("cp.async.wait_group %0;" :: "n"(N) : "memory");
}

// ---------------------------------------------------------------------------
// Prep: tf32-round x and all weights once.
// ---------------------------------------------------------------------------
__global__ __launch_bounds__(256) void prep_kernel(
    const float* __restrict__ x,  const float* __restrict__ wq,
    const float* __restrict__ wk, const float* __restrict__ wv,
    const float* __restrict__ wo)
{
    const float* src; float* dst; int n4;
    switch (blockIdx.y) {
        case 0: src = x;  dst = g_xc;  n4 = M_TOT * D_DIM / 4; break;
        case 1: src = wq; dst = g_wqc; n4 = D_DIM * D_DIM / 4; break;
        case 2: src = wk; dst = g_wkc; n4 = D_DIM * D_DIM / 4; break;
        case 3: src = wv; dst = g_wvc; n4 = D_DIM * D_DIM / 4; break;
        default: src = wo; dst = g_woc; n4 = D_DIM * D_DIM / 4; break;
    }
    const int stride = gridDim.x * blockDim.x;
    for (int i = blockIdx.x * blockDim.x + threadIdx.x; i < n4; i += stride) {
        float4 v = __ldg((const float4*)src + i);
        ((float4*)dst)[i] = make_float4(u2f(f2tf(v.x)), u2f(f2tf(v.y)),
                                        u2f(f2tf(v.z)), u2f(f2tf(v.w)));
    }
}

// ---------------------------------------------------------------------------
// GEMM core: D[128,128] = A[128,1024] @ B[128,1024]^T, tf32 inputs (pre-rounded)
// 256 thr, 8 warps 4(m)x2(n), warp tile 32x64; cp.async double-buffered kc=32.
// SMEM: A[2][128][36] + B[2][128][36] floats = 73728 B.
// ---------------------------------------------------------------------------
#define GEMM_SMEM 73728
#define A_ST 4608        // floats per A stage
#define B_OFF 9216

__device__ __forceinline__ void gemm_stage(
    uint32_t sbase, int buf, const float* __restrict__ Ag,
    const float* __restrict__ Bg, int ch)
{
    const int tid = threadIdx.x;
    #pragma unroll
    for (int t = 0; t < 4; t++) {
        int i = tid + t * 256, row = i >> 3, c4 = i & 7;
        cpa16(sbase + (buf * A_ST + row * 36 + c4 * 4) * 4,
              Ag + (size_t)row * D_DIM + ch * 32 + c4 * 4);
    }
    #pragma unroll
    for (int t = 0; t < 4; t++) {
        int i = tid + t * 256, row = i >> 3, c4 = i & 7;
        cpa16(sbase + (B_OFF + buf * A_ST + row * 36 + c4 * 4) * 4,
              Bg + (size_t)row * D_DIM + ch * 32 + c4 * 4);
    }
    cpa_commit();
}

__device__ __forceinline__ void gemm128_core(
    const float* __restrict__ Ag, const float* __restrict__ Bg,
    float C[2][8][4], float* sm)
{
    const uint32_t sbase = smem_u32(sm);
    const int tid = threadIdx.x, wid = tid >> 5, lane = tid & 31;
    const int gq = lane >> 2, qi = lane & 3;
    const int wm = (wid >> 1) * 32, wn = (wid & 1) * 64;

    #pragma unroll
    for (int mi = 0; mi < 2; mi++)
        #pragma unroll
        for (int nt = 0; nt < 8; nt++)
            #pragma unroll
            for (int r = 0; r < 4; r++) C[mi][nt][r] = 0.f;

    gemm_stage(sbase, 0, Ag, Bg, 0);

    #pragma unroll 1
    for (int ch = 0; ch < 32; ch++) {
        if (ch < 31) {
            gemm_stage(sbase, (ch + 1) & 1, Ag, Bg, ch + 1);
            cpa_wait<1>();
        } else {
            cpa_wait<0>();
        }
        __syncthreads();
        const float* as = sm + (ch & 1) * A_ST;
        const float* bs = sm + B_OFF + (ch & 1) * A_ST;
        #pragma unroll
        for (int ks = 0; ks < 4; ks++) {
            uint32_t a[2][4];
            #pragma unroll
            for (int mi = 0; mi < 2; mi++) {
                const float* p = as + (wm + 16 * mi + gq) * 36 + 8 * ks + qi;
                a[mi][0] = fbits(p[0]);
                a[mi][1] = fbits(p[8 * 36]);
                a[mi][2] = fbits(p[4]);
                a[mi][3] = fbits(p[8 * 36 + 4]);
            }
            #pragma unroll
            for (int nt = 0; nt < 8; nt++) {
                const float* p = bs + (wn + 8 * nt + gq) * 36 + 8 * ks + qi;
                uint32_t b[2] = { fbits(p[0]), fbits(p[4]) };
                mma_tf32(C[0][nt], a[0], b);
                mma_tf32(C[1][nt], a[1], b);
            }
        }
        __syncthreads();
    }
}

// ---------------------------------------------------------------------------
// Kernel 1: fused QKV projection. grid=(8, 32, 3)
// ---------------------------------------------------------------------------
__global__ __launch_bounds__(256, 2) void qkv_kernel()
{
    extern __shared__ float sm[];
    const int z = blockIdx.z;
    const float* w = (z == 0) ? g_wqc : ((z == 1) ? g_wkc : g_wvc);
    const int m0 = blockIdx.y * 128, n0 = blockIdx.x * 128;

    float C[2][8][4];
    gemm128_core(g_xc + (size_t)m0 * D_DIM, w + (size_t)n0 * D_DIM, C, sm);

    float* dst = (z == 0) ? g_q : ((z == 1) ? g_k : g_v);
    const float scale = (z == 0) ? 0.125f : 1.0f;

    const int tid = threadIdx.x, wid = tid >> 5, lane = tid & 31;
    const int gq = lane >> 2, qi = lane & 3;
    const int wm = (wid >> 1) * 32, wn = (wid & 1) * 64;

    #pragma unroll
    for (int mi = 0; mi < 2; mi++)
        #pragma unroll
        for (int nt = 0; nt < 8; nt++) {
            int m = m0 + wm + 16 * mi + gq;
            int n = n0 + wn + 8 * nt + 2 * qi;
            int h = n >> 6, hd = n & 63, bb = m >> 11, s = m & (S_LEN - 1);
            float* p0 = dst + (((size_t)bb * NH + h) * S_LEN + s) * HDIM + hd;
            float* p1 = dst + (((size_t)bb * NH + h) * S_LEN + s + 8) * HDIM + hd;
            *(float2*)p0 = make_float2(u2f(f2tf(C[mi][nt][0] * scale)),
                                       u2f(f2tf(C[mi][nt][1] * scale)));
            *(float2*)p1 = make_float2(u2f(f2tf(C[mi][nt][2] * scale)),
                                       u2f(f2tf(C[mi][nt][3] * scale)));
        }
}

// ---------------------------------------------------------------------------
// Kernel 3: output projection + bias. grid=(8, 32)
// ---------------------------------------------------------------------------
__global__ __launch_bounds__(256, 2) void oproj_kernel(
    const float* __restrict__ bo, float* __restrict__ out)
{
    extern __shared__ float sm[];
    const int m0 = blockIdx.y * 128, n0 = blockIdx.x * 128;

    float C[2][8][4];
    gemm128_core(g_ctx + (size_t)m0 * D_DIM, g_woc + (size_t)n0 * D_DIM, C, sm);

    const int tid = threadIdx.x, wid = tid >> 5, lane = tid & 31;
    const int gq = lane >> 2, qi = lane & 3;
    const int wm = (wid >> 1) * 32, wn = (wid & 1) * 64;

    #pragma unroll
    for (int mi = 0; mi < 2; mi++)
        #pragma unroll
        for (int nt = 0; nt < 8; nt++) {
            int m = m0 + wm + 16 * mi + gq;
            int n = n0 + wn + 8 * nt + 2 * qi;
            float b0 = __ldg(bo + n), b1 = __ldg(bo + n + 1);
            *(float2*)(out + (size_t)m * D_DIM + n) =
                make_float2(C[mi][nt][0] + b0, C[mi][nt][1] + b1);
            *(float2*)(out + (size_t)(m + 8) * D_DIM + n) =
                make_float2(C[mi][nt][2] + b0, C[mi][nt][3] + b1);
        }
}

// ---------------------------------------------------------------------------
// Kernel 2: flash attention, 512 threads / CTA, 16 warps 4(m)x4(n).
// Warp S-tile 32x32, O-tile 32x16. grid=(16, B*NH).
// ---------------------------------------------------------------------------
#define ATTN_SMEM ((128*68 + 128*68 + 128*72 + 128*132 + 1024) * 4)  // 178176 B

__global__ __launch_bounds__(512, 1) void attn_kernel()
{
    extern __shared__ float sm[];
    float* Qs   = sm;                    // [128][68] (only 64 cols used)
    float* Ks   = Qs + 128 * 68;         // [128][68]
    float* Vs   = Ks + 128 * 68;         // [128][72]
    float* Ps   = Vs + 128 * 72;         // [128][132]
    float* redm = Ps + 128 * 132;        // [4][128]
    float* reds = redm + 512;            // [4][128]

    const int bh = blockIdx.y, qt = blockIdx.x;
    const int tid = threadIdx.x, wid = tid >> 5, lane = tid & 31;
    const int gq = lane >> 2, qi = lane & 3;
    const int wm = (wid >> 2) * 32;
    const int nh = wid & 3;
    const int wn = nh * 32;     // S key-column offset
    const int wo = nh * 16;     // O hd-column offset

    const float* qp = g_q + ((size_t)bh * S_LEN + qt * 128) * HDIM;
    const float* kp = g_k + (size_t)bh * S_LEN * HDIM;
    const float* vp = g_v + (size_t)bh * S_LEN * HDIM;

    {   // Q tile 128x64
        const int r = tid >> 4, c = (tid & 15) << 2;
        #pragma unroll
        for (int j = 0; j < 4; j++)
            *(float4*)(Qs + (r + 32 * j) * 68 + c) =
                *(const float4*)(qp + (size_t)(r + 32 * j) * HDIM + c);
    }

    float O[2][2][4];
    float m_i[4], l_i[4];
    #pragma unroll
    for (int i = 0; i < 4; i++) { m_i[i] = -1e30f; l_i[i] = 0.f; }
    #pragma unroll
    for (int mi = 0; mi < 2; mi++)
        #pragma unroll
        for (int ni = 0; ni < 2; ni++)
            #pragma unroll
            for (int r = 0; r < 4; r++) O[mi][ni][r] = 0.f;

    #pragma unroll 1
    for (int kt = 0; kt < S_LEN / 128; kt++) {
        __syncthreads();
        {
            const int r = tid >> 4, c = (tid & 15) << 2;
            #pragma unroll
            for (int j = 0; j < 4; j++) {
                *(float4*)(Ks + (r + 32 * j) * 68 + c) =
                    *(const float4*)(kp + (size_t)(kt * 128 + r + 32 * j) * HDIM + c);
                *(float4*)(Vs + (r + 32 * j) * 72 + c) =
                    *(const float4*)(vp + (size_t)(kt * 128 + r + 32 * j) * HDIM + c);
            }
        }
        __syncthreads();

        // S = Q @ K^T : warp tile rows wm..wm+31, cols wn..wn+31
        float Cs[2][4][4];
        #pragma unroll
        for (int mi = 0; mi < 2; mi++)
            #pragma unroll
            for (int nt = 0; nt < 4; nt++)
                #pragma unroll
                for (int r = 0; r < 4; r++) Cs[mi][nt][r] = 0.f;

        #pragma unroll
        for (int ks = 0; ks < 8; ks++) {
            uint32_t a[2][4];
            #pragma unroll
            for (int mi = 0; mi < 2; mi++) {
                const float* p = Qs + (wm + 16 * mi + gq) * 68 + 8 * ks + qi;
                a[mi][0] = fbits(p[0]);
                a[mi][1] = fbits(p[8 * 68]);
                a[mi][2] = fbits(p[4]);
                a[mi][3] = fbits(p[8 * 68 + 4]);
            }
            #pragma unroll
            for (int nt = 0; nt < 4; nt++) {
                const float* p = Ks + (wn + 8 * nt + gq) * 68 + 8 * ks + qi;
                uint32_t b[2] = { fbits(p[0]), fbits(p[4]) };
                mma_tf32(Cs[0][nt], a[0], b);
                mma_tf32(Cs[1][nt], a[1], b);
            }
        }

        // partial row max (each warp covers 32 of 128 cols)
        #pragma unroll
        for (int i = 0; i < 4; i++) {
            int mi = i >> 1, hf = i & 1;
            float v = Cs[mi][0][2 * hf];
            #pragma unroll
            for (int nt = 0; nt < 4; nt++) {
                v = fmaxf(v, Cs[mi][nt][2 * hf]);
                v = fmaxf(v, Cs[mi][nt][2 * hf + 1]);
            }
            v = fmaxf(v, __shfl_xor_sync(0xffffffffu, v, 1));
            v = fmaxf(v, __shfl_xor_sync(0xffffffffu, v, 2));
            if (qi == 0) redm[nh * 128 + wm + 16 * mi + 8 * hf + gq] = v;
        }
        __syncthreads();

        float mn[4], corr[4];
        #pragma unroll
        for (int i = 0; i < 4; i++) {
            int row = wm + 16 * (i >> 1) + 8 * (i & 1) + gq;
            float gm = fmaxf(fmaxf(redm[row], redm[128 + row]),
                             fmaxf(redm[256 + row], redm[384 + row]));
            mn[i] = fmaxf(m_i[i], gm);
            corr[i] = __expf(m_i[i] - mn[i]);
            m_i[i] = mn[i];
        }

        // exp + partial sums
        float ps[4] = {0.f, 0.f, 0.f, 0.f};
        #pragma unroll
        for (int mi = 0; mi < 2; mi++)
            #pragma unroll
            for (int nt = 0; nt < 4; nt++)
                #pragma unroll
                for (int hf = 0; hf < 2; hf++) {
                    float e0 = __expf(Cs[mi][nt][2 * hf]     - mn[2 * mi + hf]);
                    float e1 = __expf(Cs[mi][nt][2 * hf + 1] - mn[2 * mi + hf]);
                    Cs[mi][nt][2 * hf] = e0; Cs[mi][nt][2 * hf + 1] = e1;
                    ps[2 * mi + hf] += e0 + e1;
                }
        #pragma unroll
        for (int i = 0; i < 4; i++) {
            float v = ps[i];
            v += __shfl_xor_sync(0xffffffffu, v, 1);
            v += __shfl_xor_sync(0xffffffffu, v, 2);
            if (qi == 0) reds[nh * 128 + wm + 16 * (i >> 1) + 8 * (i & 1) + gq] = v;
        }

        // rescale O
        #pragma unroll
        for (int mi = 0; mi < 2; mi++)
            #pragma unroll
            for (int ni = 0; ni < 2; ni++) {
                O[mi][ni][0] *= corr[2 * mi];     O[mi][ni][1] *= corr[2 * mi];
                O[mi][ni][2] *= corr[2 * mi + 1]; O[mi][ni][3] *= corr[2 * mi + 1];
            }

        // store P (tf32-rounded)
        #pragma unroll
        for (int mi = 0; mi < 2; mi++)
            #pragma unroll
            for (int nt = 0; nt < 4; nt++) {
                int row = wm + 16 * mi + gq, col = wn + 8 * nt + 2 * qi;
                *(float2*)(Ps + row * 132 + col) =
                    make_float2(u2f(f2tf(Cs[mi][nt][0])), u2f(f2tf(Cs[mi][nt][1])));
                *(float2*)(Ps + (row + 8) * 132 + col) =
                    make_float2(u2f(f2tf(Cs[mi][nt][2])), u2f(f2tf(Cs[mi][nt][3])));
            }
        __syncthreads();

        #pragma unroll
        for (int i = 0; i < 4; i++) {
            int row = wm + 16 * (i >> 1) + 8 * (i & 1) + gq;
            l_i[i] = l_i[i] * corr[i] + reds[row] + reds[128 + row]
                   + reds[256 + row] + reds[384 + row];
        }

        // O += P @ V : warp rows wm..wm+31, hd cols wo..wo+15
        #pragma unroll
        for (int ks = 0; ks < 16; ks++) {
            uint32_t a[2][4];
            #pragma unroll
            for (int mi = 0; mi < 2; mi++) {
                const float* p = Ps + (wm + 16 * mi + gq) * 132 + 8 * ks + qi;
                a[mi][0] = fbits(p[0]);
                a[mi][1] = fbits(p[8 * 132]);
                a[mi][2] = fbits(p[4]);
                a[mi][3] = fbits(p[8 * 132 + 4]);
            }
            #pragma unroll
            for (int ni = 0; ni < 2; ni++) {
                const float* p = Vs + (size_t)(8 * ks + qi) * 72 + wo + 8 * ni + gq;
                uint32_t b[2] = { fbits(p[0]), fbits(p[4 * 72]) };
                mma_tf32(O[0][ni], a[0], b);
                mma_tf32(O[1][ni], a[1], b);
            }
        }
    }

    // epilogue: normalize + write ctx [b,s,h,hd] (tf32-rounded for oproj cp.async)
    const int b_ = bh >> 4, h = bh & 15;
    #pragma unroll
    for (int mi = 0; mi < 2; mi++) {
        float inv0 = 1.f / l_i[2 * mi], inv1 = 1.f / l_i[2 * mi + 1];
        int s = qt * 128 + wm + 16 * mi + gq;
        #pragma unroll
        for (int ni = 0; ni < 2; ni++) {
            int cc = wo + 8 * ni + 2 * qi;
            float* p0 = g_ctx + (((size_t)b_ * S_LEN + s) * NH + h) * HDIM + cc;
            float* p1 = g_ctx + (((size_t)b_ * S_LEN + s + 8) * NH + h) * HDIM + cc;
            *(float2*)p0 = make_float2(u2f(f2tf(O[mi][ni][0] * inv0)),
                                       u2f(f2tf(O[mi][ni][1] * inv0)));
            *(float2*)p1 = make_float2(u2f(f2tf(O[mi][ni][2] * inv1)),
                                       u2f(f2tf(O[mi][ni][3] * inv1)));
        }
    }
}

// ---------------------------------------------------------------------------
extern "C" void kernel_launch(void* const* d_in, const int* in_sizes, int n_in,
                              void* d_out, int out_size)
{
    const float* x  = (const float*)d_in[0];
    const float* wq = (const float*)d_in[1];
    const float* wk = (const float*)d_in[2];
    const float* wv = (const float*)d_in[3];
    const float* wo = (const float*)d_in[4];
    const float* bo = (const float*)d_in[5];
    float* out = (float*)d_out;

    cudaFuncSetAttribute(qkv_kernel,   cudaFuncAttributeMaxDynamicSharedMemorySize, GEMM_SMEM);
    cudaFuncSetAttribute(oproj_kernel, cudaFuncAttributeMaxDynamicSharedMemorySize, GEMM_SMEM);
    cudaFuncSetAttribute(attn_kernel,  cudaFuncAttributeMaxDynamicSharedMemorySize, ATTN_SMEM);

    prep_kernel<<<dim3(256, 5), 256>>>(x, wq, wk, wv, wo);
    qkv_kernel<<<dim3(D_DIM / 128, M_TOT / 128, 3), 256, GEMM_SMEM>>>();
    attn_kernel<<<dim3(S_LEN / 128, NB * NH), 512, ATTN_SMEM>>>();
    oproj_kernel<<<dim3(D_DIM / 128, M_TOT / 128), 256, GEMM_SMEM>>>(bo, out);
}

// round 5
// speedup vs baseline: 1.0493x; 1.0493x over previous
#include <cuda_runtime.h>
#include <cstdint>

#define S_LEN 2048
#define D_DIM 1024
#define NH    16
#define HDIM  64
#define NB    2
#define M_TOT 4096

// Scratch
__device__ float g_q[NB * NH * S_LEN * HDIM];   // [b,h,s,hd], pre-scaled 0.125, tf32
__device__ float g_k[NB * NH * S_LEN * HDIM];
__device__ float g_v[NB * NH * S_LEN * HDIM];
__device__ float g_ctx[NB * S_LEN * D_DIM];     // [b,s,d], tf32-rounded
__device__ float g_xc[M_TOT * D_DIM];           // tf32-rounded inputs
__device__ float g_wqc[D_DIM * D_DIM];
__device__ float g_wkc[D_DIM * D_DIM];
__device__ float g_wvc[D_DIM * D_DIM];
__device__ float g_woc[D_DIM * D_DIM];

// ---------------------------------------------------------------------------
__device__ __forceinline__ uint32_t f2tf(float f) {
    uint32_t u;
    asm("cvt.rna.tf32.f32 %0, %1;" : "=r"(u) : "f"(f));
    return u;
}
__device__ __forceinline__ float u2f(uint32_t u) { return __uint_as_float(u); }
__device__ __forceinline__ uint32_t fbits(float f) { return __float_as_uint(f); }

__device__ __forceinline__ uint32_t smem_u32(const void* p) {
    uint32_t a;
    asm("{ .reg .u64 t; cvta.to.shared.u64 t, %1; cvt.u32.u64 %0, t; }" : "=r"(a) : "l"(p));
    return a;
}
__device__ __forceinline__ void mma_tf32(float d[4], const uint32_t a[4], const uint32_t b[2]) {
    asm("mma.sync.aligned.m16n8k8.row.col.f32.tf32.tf32.f32 "
        "{%0,%1,%2,%3}, {%4,%5,%6,%7}, {%8,%9}, {%0,%1,%2,%3};"
        : "+f"(d[0]), "+f"(d[1]), "+f"(d[2]), "+f"(d[3])
        : "r"(a[0]), "r"(a[1]), "r"(a[2]), "r"(a[3]), "r"(b[0]), "r"(b[1]));
}
__device__ __forceinline__ void cpa16(uint32_t dst, const void* src) {
    asm volatile("cp.async.ca.shared.global [%0], [%1], 16;" :: "r"(dst), "l"(src) : "memory");
}
__device__ __forceinline__ void cpa_commit() {
    asm volatile("cp.async.commit_group;" ::: "memory");
}
template <int N>
__device__ __forceinline__ void cpa_wait() {
    asm volatile("cp.async.wait_group %0;" :: "n"(N) : "memory");
}

// ---------------------------------------------------------------------------
// Prep: tf32-round x and all weights once.
// ---------------------------------------------------------------------------
__global__ __launch_bounds__(256) void prep_kernel(
    const float* __restrict__ x,  const float* __restrict__ wq,
    const float* __restrict__ wk, const float* __restrict__ wv,
    const float* __restrict__ wo)
{
    const float* src; float* dst; int n4;
    switch (blockIdx.y) {
        case 0: src = x;  dst = g_xc;  n4 = M_TOT * D_DIM / 4; break;
        case 1: src = wq; dst = g_wqc; n4 = D_DIM * D_DIM / 4; break;
        case 2: src = wk; dst = g_wkc; n4 = D_DIM * D_DIM / 4; break;
        case 3: src = wv; dst = g_wvc; n4 = D_DIM * D_DIM / 4; break;
        default: src = wo; dst = g_woc; n4 = D_DIM * D_DIM / 4; break;
    }
    const int stride = gridDim.x * blockDim.x;
    for (int i = blockIdx.x * blockDim.x + threadIdx.x; i < n4; i += stride) {
        float4 v = __ldg((const float4*)src + i);
        ((float4*)dst)[i] = make_float4(u2f(f2tf(v.x)), u2f(f2tf(v.y)),
                                        u2f(f2tf(v.z)), u2f(f2tf(v.w)));
    }
}

// ---------------------------------------------------------------------------
// GEMM core: D[128,128] = A[128,1024] @ B[128,1024]^T, pre-rounded tf32 inputs.
// 256 thr, 8 warps 4(m)x2(n), warp tile 32x64; 3-stage cp.async, 1 sync/chunk.
// ---------------------------------------------------------------------------
#define GS_A   4608                    // floats per stage (128*36)
#define GB_OFF (3 * GS_A)              // B region float offset
#define GEMM_SMEM (6 * GS_A * 4)       // 110592 B

__device__ __forceinline__ void gemm_stage(
    uint32_t sbase, int buf, const float* __restrict__ Ag,
    const float* __restrict__ Bg, int ch)
{
    const int tid = threadIdx.x;
    #pragma unroll
    for (int t = 0; t < 4; t++) {
        int i = tid + t * 256, row = i >> 3, c4 = i & 7;
        cpa16(sbase + (buf * GS_A + row * 36 + c4 * 4) * 4,
              Ag + (size_t)row * D_DIM + ch * 32 + c4 * 4);
    }
    #pragma unroll
    for (int t = 0; t < 4; t++) {
        int i = tid + t * 256, row = i >> 3, c4 = i & 7;
        cpa16(sbase + (GB_OFF + buf * GS_A + row * 36 + c4 * 4) * 4,
              Bg + (size_t)row * D_DIM + ch * 32 + c4 * 4);
    }
    cpa_commit();
}

__device__ __forceinline__ void gemm128_core(
    const float* __restrict__ Ag, const float* __restrict__ Bg,
    float C[2][8][4], float* sm)
{
    const uint32_t sbase = smem_u32(sm);
    const int tid = threadIdx.x, wid = tid >> 5, lane = tid & 31;
    const int gq = lane >> 2, qi = lane & 3;
    const int wm = (wid >> 1) * 32, wn = (wid & 1) * 64;

    #pragma unroll
    for (int mi = 0; mi < 2; mi++)
        #pragma unroll
        for (int nt = 0; nt < 8; nt++)
            #pragma unroll
            for (int r = 0; r < 4; r++) C[mi][nt][r] = 0.f;

    gemm_stage(sbase, 0, Ag, Bg, 0);
    gemm_stage(sbase, 1, Ag, Bg, 1);

    int buf = 0, nbuf = 2;
    #pragma unroll 1
    for (int ch = 0; ch < 32; ch++) {
        if (ch == 31) cpa_wait<0>(); else cpa_wait<1>();
        __syncthreads();
        if (ch + 2 < 32) gemm_stage(sbase, nbuf, Ag, Bg, ch + 2);

        const float* as = sm + buf * GS_A;
        const float* bs = sm + GB_OFF + buf * GS_A;
        #pragma unroll
        for (int ks = 0; ks < 4; ks++) {
            uint32_t a[2][4];
            #pragma unroll
            for (int mi = 0; mi < 2; mi++) {
                const float* p = as + (wm + 16 * mi + gq) * 36 + 8 * ks + qi;
                a[mi][0] = fbits(p[0]);
                a[mi][1] = fbits(p[8 * 36]);
                a[mi][2] = fbits(p[4]);
                a[mi][3] = fbits(p[8 * 36 + 4]);
            }
            #pragma unroll
            for (int nt = 0; nt < 8; nt++) {
                const float* p = bs + (wn + 8 * nt + gq) * 36 + 8 * ks + qi;
                uint32_t b[2] = { fbits(p[0]), fbits(p[4]) };
                mma_tf32(C[0][nt], a[0], b);
                mma_tf32(C[1][nt], a[1], b);
            }
        }
        buf = (buf == 2) ? 0 : buf + 1;
        nbuf = (nbuf == 2) ? 0 : nbuf + 1;
    }
}

// ---------------------------------------------------------------------------
// Kernel 1: fused QKV projection. grid=(8, 32, 3)
// ---------------------------------------------------------------------------
__global__ __launch_bounds__(256, 2) void qkv_kernel()
{
    extern __shared__ float sm[];
    const int z = blockIdx.z;
    const float* w = (z == 0) ? g_wqc : ((z == 1) ? g_wkc : g_wvc);
    const int m0 = blockIdx.y * 128, n0 = blockIdx.x * 128;

    float C[2][8][4];
    gemm128_core(g_xc + (size_t)m0 * D_DIM, w + (size_t)n0 * D_DIM, C, sm);

    float* dst = (z == 0) ? g_q : ((z == 1) ? g_k : g_v);
    const float scale = (z == 0) ? 0.125f : 1.0f;

    const int tid = threadIdx.x, wid = tid >> 5, lane = tid & 31;
    const int gq = lane >> 2, qi = lane & 3;
    const int wm = (wid >> 1) * 32, wn = (wid & 1) * 64;

    #pragma unroll
    for (int mi = 0; mi < 2; mi++)
        #pragma unroll
        for (int nt = 0; nt < 8; nt++) {
            int m = m0 + wm + 16 * mi + gq;
            int n = n0 + wn + 8 * nt + 2 * qi;
            int h = n >> 6, hd = n & 63, bb = m >> 11, s = m & (S_LEN - 1);
            float* p0 = dst + (((size_t)bb * NH + h) * S_LEN + s) * HDIM + hd;
            float* p1 = dst + (((size_t)bb * NH + h) * S_LEN + s + 8) * HDIM + hd;
            *(float2*)p0 = make_float2(u2f(f2tf(C[mi][nt][0] * scale)),
                                       u2f(f2tf(C[mi][nt][1] * scale)));
            *(float2*)p1 = make_float2(u2f(f2tf(C[mi][nt][2] * scale)),
                                       u2f(f2tf(C[mi][nt][3] * scale)));
        }
}

// ---------------------------------------------------------------------------
// Kernel 3: output projection + bias. grid=(8, 32)
// ---------------------------------------------------------------------------
__global__ __launch_bounds__(256, 2) void oproj_kernel(
    const float* __restrict__ bo, float* __restrict__ out)
{
    extern __shared__ float sm[];
    const int m0 = blockIdx.y * 128, n0 = blockIdx.x * 128;

    float C[2][8][4];
    gemm128_core(g_ctx + (size_t)m0 * D_DIM, g_woc + (size_t)n0 * D_DIM, C, sm);

    const int tid = threadIdx.x, wid = tid >> 5, lane = tid & 31;
    const int gq = lane >> 2, qi = lane & 3;
    const int wm = (wid >> 1) * 32, wn = (wid & 1) * 64;

    #pragma unroll
    for (int mi = 0; mi < 2; mi++)
        #pragma unroll
        for (int nt = 0; nt < 8; nt++) {
            int m = m0 + wm + 16 * mi + gq;
            int n = n0 + wn + 8 * nt + 2 * qi;
            float b0 = __ldg(bo + n), b1 = __ldg(bo + n + 1);
            *(float2*)(out + (size_t)m * D_DIM + n) =
                make_float2(C[mi][nt][0] + b0, C[mi][nt][1] + b1);
            *(float2*)(out + (size_t)(m + 8) * D_DIM + n) =
                make_float2(C[mi][nt][2] + b0, C[mi][nt][3] + b1);
        }
}

// ---------------------------------------------------------------------------
// Kernel 2: flash attention, 512 thr, 16 warps = 8(m of 16 rows) x 2(kv half).
// P kept in registers (shuffle transpose C-frag -> A-frag). K/V cp.async
// double-buffered. Final O combine across the 2 kv-halves via SMEM.
// ---------------------------------------------------------------------------
#define AQ_OFF 0
#define AK_OFF 8704                    // Qs: 128*68
#define AV_OFF (AK_OFF + 2 * 8704)     // Ks: 2 stages of 128*68
#define AR_OFF (AV_OFF + 2 * 9216)     // Vs: 2 stages of 128*72
#define ATTN_SMEM ((AR_OFF + 512) * 4) // + redm[2][128], reds[2][128] = 180224 B

__device__ __forceinline__ void attn_prefetch(
    uint32_t sbase, const float* __restrict__ kp, const float* __restrict__ vp, int kt)
{
    const int tid = threadIdx.x;
    const int st = kt & 1;
    #pragma unroll
    for (int t = 0; t < 4; t++) {
        int i = tid + t * 512, row = i >> 4, c4 = i & 15;
        cpa16(sbase + (AK_OFF + st * 8704 + row * 68 + c4 * 4) * 4,
              kp + (size_t)(kt * 128 + row) * HDIM + c4 * 4);
    }
    #pragma unroll
    for (int t = 0; t < 4; t++) {
        int i = tid + t * 512, row = i >> 4, c4 = i & 15;
        cpa16(sbase + (AV_OFF + st * 9216 + row * 72 + c4 * 4) * 4,
              vp + (size_t)(kt * 128 + row) * HDIM + c4 * 4);
    }
    cpa_commit();
}

// C-fragment (exp'd scores) -> A-fragment for the PV mma, tf32-rounded.
__device__ __forceinline__ void p_to_afrag(const float c[4], uint32_t a[4], int lane) {
    const int qi = lane & 3;
    const int s0 = (lane & ~3) | (qi >> 1);
    const int s1 = s0 + 2;
    float t0 = __shfl_sync(0xffffffffu, c[0], s0);
    float t1 = __shfl_sync(0xffffffffu, c[1], s0);
    float t2 = __shfl_sync(0xffffffffu, c[2], s0);
    float t3 = __shfl_sync(0xffffffffu, c[3], s0);
    float u0 = __shfl_sync(0xffffffffu, c[0], s1);
    float u1 = __shfl_sync(0xffffffffu, c[1], s1);
    float u2 = __shfl_sync(0xffffffffu, c[2], s1);
    float u3 = __shfl_sync(0xffffffffu, c[3], s1);
    const bool odd = qi & 1;
    a[0] = f2tf(odd ? t1 : t0);
    a[1] = f2tf(odd ? t3 : t2);
    a[2] = f2tf(odd ? u1 : u0);
    a[3] = f2tf(odd ? u3 : u2);
}

__global__ __launch_bounds__(512, 1) void attn_kernel()
{
    extern __shared__ float sm[];
    float* Qs   = sm + AQ_OFF;           // [128][68]
    float* redm = sm + AR_OFF;           // [2][128]
    float* reds = redm + 256;            // [2][128]
    const uint32_t sbase = smem_u32(sm);

    const int bh = blockIdx.y, qt = blockIdx.x;
    const int tid = threadIdx.x, wid = tid >> 5, lane = tid & 31;
    const int gq = lane >> 2, qi = lane & 3;
    const int wm  = (wid >> 1) * 16;     // 16-row m tile
    const int kvh = wid & 1;
    const int wn  = kvh * 64;            // 64-key slice

    const float* qp = g_q + ((size_t)bh * S_LEN + qt * 128) * HDIM;
    const float* kp = g_k + (size_t)bh * S_LEN * HDIM;
    const float* vp = g_v + (size_t)bh * S_LEN * HDIM;

    // prefetch tile 0; load Q while it flies
    attn_prefetch(sbase, kp, vp, 0);
    #pragma unroll
    for (int t = 0; t < 4; t++) {
        int i = tid + t * 512, row = i >> 4, c4 = i & 15;
        *(float4*)(Qs + row * 68 + c4 * 4) =
            *(const float4*)(qp + (size_t)row * HDIM + c4 * 4);
    }

    float O[8][4];
    float m_i[2] = { -1e30f, -1e30f }, l_i[2] = { 0.f, 0.f };
    #pragma unroll
    for (int nt = 0; nt < 8; nt++)
        #pragma unroll
        for (int r = 0; r < 4; r++) O[nt][r] = 0.f;

    #pragma unroll 1
    for (int kt = 0; kt < S_LEN / 128; kt++) {
        cpa_wait<0>();
        __syncthreads();                     // tile kt visible; prev iter fully done
        if (kt + 1 < S_LEN / 128) attn_prefetch(sbase, kp, vp, kt + 1);

        const float* ks = sm + AK_OFF + (kt & 1) * 8704;
        const float* vs = sm + AV_OFF + (kt & 1) * 9216;

        // S = Q @ K^T : rows wm..wm+15, cols wn..wn+63
        float Cs[8][4];
        #pragma unroll
        for (int nt = 0; nt < 8; nt++)
            #pragma unroll
            for (int r = 0; r < 4; r++) Cs[nt][r] = 0.f;

        #pragma unroll
        for (int ks_ = 0; ks_ < 8; ks_++) {
            uint32_t a[4];
            const float* p = Qs + (wm + gq) * 68 + 8 * ks_ + qi;
            a[0] = fbits(p[0]);
            a[1] = fbits(p[8 * 68]);
            a[2] = fbits(p[4]);
            a[3] = fbits(p[8 * 68 + 4]);
            #pragma unroll
            for (int nt = 0; nt < 8; nt++) {
                const float* pb = ks + (wn + 8 * nt + gq) * 68 + 8 * ks_ + qi;
                uint32_t b[2] = { fbits(pb[0]), fbits(pb[4]) };
                mma_tf32(Cs[nt], a, b);
            }
        }

        // partial row max over 64-col slice, rows gq / gq+8
        float rm0 = Cs[0][0], rm1 = Cs[0][2];
        #pragma unroll
        for (int nt = 0; nt < 8; nt++) {
            rm0 = fmaxf(rm0, fmaxf(Cs[nt][0], Cs[nt][1]));
            rm1 = fmaxf(rm1, fmaxf(Cs[nt][2], Cs[nt][3]));
        }
        rm0 = fmaxf(rm0, __shfl_xor_sync(0xffffffffu, rm0, 1));
        rm0 = fmaxf(rm0, __shfl_xor_sync(0xffffffffu, rm0, 2));
        rm1 = fmaxf(rm1, __shfl_xor_sync(0xffffffffu, rm1, 1));
        rm1 = fmaxf(rm1, __shfl_xor_sync(0xffffffffu, rm1, 2));
        if (qi == 0) {
            redm[kvh * 128 + wm + gq]     = rm0;
            redm[kvh * 128 + wm + gq + 8] = rm1;
        }
        __syncthreads();

        float mn0 = fmaxf(m_i[0], fmaxf(redm[wm + gq],     redm[128 + wm + gq]));
        float mn1 = fmaxf(m_i[1], fmaxf(redm[wm + gq + 8], redm[128 + wm + gq + 8]));
        float corr0 = __expf(m_i[0] - mn0), corr1 = __expf(m_i[1] - mn1);
        m_i[0] = mn0; m_i[1] = mn1;

        float ps0 = 0.f, ps1 = 0.f;
        #pragma unroll
        for (int nt = 0; nt < 8; nt++) {
            float e0 = __expf(Cs[nt][0] - mn0), e1 = __expf(Cs[nt][1] - mn0);
            float e2 = __expf(Cs[nt][2] - mn1), e3 = __expf(Cs[nt][3] - mn1);
            Cs[nt][0] = e0; Cs[nt][1] = e1; Cs[nt][2] = e2; Cs[nt][3] = e3;
            ps0 += e0 + e1; ps1 += e2 + e3;
        }
        ps0 += __shfl_xor_sync(0xffffffffu, ps0, 1);
        ps0 += __shfl_xor_sync(0xffffffffu, ps0, 2);
        ps1 += __shfl_xor_sync(0xffffffffu, ps1, 1);
        ps1 += __shfl_xor_sync(0xffffffffu, ps1, 2);
        if (qi == 0) {
            reds[kvh * 128 + wm + gq]     = ps0;
            reds[kvh * 128 + wm + gq + 8] = ps1;
        }

        // rescale O while reds lands
        #pragma unroll
        for (int nt = 0; nt < 8; nt++) {
            O[nt][0] *= corr0; O[nt][1] *= corr0;
            O[nt][2] *= corr1; O[nt][3] *= corr1;
        }
        __syncthreads();

        l_i[0] = l_i[0] * corr0 + reds[wm + gq]     + reds[128 + wm + gq];
        l_i[1] = l_i[1] * corr1 + reds[wm + gq + 8] + reds[128 + wm + gq + 8];

        // O += P @ V over this warp's 64-key slice, full HD=64
        #pragma unroll
        for (int kc = 0; kc < 8; kc++) {
            uint32_t a[4];
            p_to_afrag(Cs[kc], a, lane);
            const float* pv = vs + (size_t)(wn + 8 * kc + qi) * 72 + gq;
            #pragma unroll
            for (int nt = 0; nt < 8; nt++) {
                uint32_t b[2] = { fbits(pv[8 * nt]), fbits(pv[4 * 72 + 8 * nt]) };
                mma_tf32(O[nt], a, b);
            }
        }
    }

    // Combine the two kv-halves' O, normalize, write ctx [b,s,h,hd].
    __syncthreads();                       // everyone out of mainloop (Qs reuse)
    float* Os = Qs;                        // [128][68] scratch
    if (kvh == 1) {
        #pragma unroll
        for (int nt = 0; nt < 8; nt++) {
            int cc = 8 * nt + 2 * qi;
            *(float2*)(Os + (wm + gq) * 68 + cc)     = make_float2(O[nt][0], O[nt][1]);
            *(float2*)(Os + (wm + gq + 8) * 68 + cc) = make_float2(O[nt][2], O[nt][3]);
        }
    }
    __syncthreads();
    if (kvh == 0) {
        const int b_ = bh >> 4, h = bh & 15;
        const float inv0 = 1.f / l_i[0], inv1 = 1.f / l_i[1];
        const int s = qt * 128 + wm + gq;
        #pragma unroll
        for (int nt = 0; nt < 8; nt++) {
            int cc = 8 * nt + 2 * qi;
            float2 q0 = *(float2*)(Os + (wm + gq) * 68 + cc);
            float2 q1 = *(float2*)(Os + (wm + gq + 8) * 68 + cc);
            float* p0 = g_ctx + (((size_t)b_ * S_LEN + s) * NH + h) * HDIM + cc;
            float* p1 = g_ctx + (((size_t)b_ * S_LEN + s + 8) * NH + h) * HDIM + cc;
            *(float2*)p0 = make_float2(u2f(f2tf((O[nt][0] + q0.x) * inv0)),
                                       u2f(f2tf((O[nt][1] + q0.y) * inv0)));
            *(float2*)p1 = make_float2(u2f(f2tf((O[nt][2] + q1.x) * inv1)),
                                       u2f(f2tf((O[nt][3] + q1.y) * inv1)));
        }
    }
}

// ---------------------------------------------------------------------------
extern "C" void kernel_launch(void* const* d_in, const int* in_sizes, int n_in,
                              void* d_out, int out_size)
{
    const float* x  = (const float*)d_in[0];
    const float* wq = (const float*)d_in[1];
    const float* wk = (const float*)d_in[2];
    const float* wv = (const float*)d_in[3];
    const float* wo = (const float*)d_in[4];
    const float* bo = (const float*)d_in[5];
    float* out = (float*)d_out;

    cudaFuncSetAttribute(qkv_kernel,   cudaFuncAttributeMaxDynamicSharedMemorySize, GEMM_SMEM);
    cudaFuncSetAttribute(oproj_kernel, cudaFuncAttributeMaxDynamicSharedMemorySize, GEMM_SMEM);
    cudaFuncSetAttribute(attn_kernel,  cudaFuncAttributeMaxDynamicSharedMemorySize, ATTN_SMEM);

    prep_kernel<<<dim3(256, 5), 256>>>(x, wq, wk, wv, wo);
    qkv_kernel<<<dim3(D_DIM / 128, M_TOT / 128, 3), 256, GEMM_SMEM>>>();
    attn_kernel<<<dim3(S_LEN / 128, NB * NH), 512, ATTN_SMEM>>>();
    oproj_kernel<<<dim3(D_DIM / 128, M_TOT / 128), 256, GEMM_SMEM>>>(bo, out);
}